// round 2
// baseline (speedup 1.0000x reference)
#include <cuda_runtime.h>
#include <cuda_bf16.h>
#include <cstdint>

// ---------------------------------------------------------------------------
// MultiAttention fused pipeline, fp32 + FFMA2 (fma.rn.f32x2).
// Round 1: kernel_launch is PURE kernel launches (no host API calls — the
// Round-0 cudaFuncSetAttribute during graph capture is the suspected cause of
// replay divergence). k_attn restructured to <=48KB STATIC shared memory.
//
//   K1: per-batch qkv GEMM (x(6,128) @ Wcat(128,384) + bcat) + attention
//       (scores = Q K^T, out = scores V, no softmax) -> g_attn, plus
//       sum/sumsq of m = concat(x, attn) per (b,s) row -> g_msum/g_msumsq.
//   K2: n = LN1(m) @ Wf + bf.   LN applied during A-tile load.
//   K2b: LN2 stats over concat(n, m) (512 dims) -> g_mu2/g_rs2.
//   K3: out = relu( LN2(concat(n,m)) @ Ws + bs ), K=3072, N=256.
// ---------------------------------------------------------------------------

#define BATCH   65536
#define ROWS6   (BATCH * 6)          // 393216
#define EPS_LN  1e-5f

// Scratch (device globals: allocation-free rule)
__device__ __align__(16) float g_attn[ROWS6 * 128];   // 201 MB
__device__ __align__(16) float g_n[ROWS6 * 256];      // 403 MB
__device__ __align__(16) float g_msum[ROWS6];
__device__ __align__(16) float g_msumsq[ROWS6];
__device__ __align__(16) float g_mu2[ROWS6];
__device__ __align__(16) float g_rs2[ROWS6];

typedef unsigned long long u64;

__device__ __forceinline__ u64 pk2(float x, float y) {
    u64 r;
    asm("mov.b64 %0, {%1, %2};" : "=l"(r) : "f"(x), "f"(y));
    return r;
}
__device__ __forceinline__ void upk2(u64 v, float& x, float& y) {
    asm("mov.b64 {%0, %1}, %2;" : "=f"(x), "=f"(y) : "l"(v));
}
// c = a*b + c (packed f32x2 -> SASS FFMA2, 2x fp32 rate)
__device__ __forceinline__ void ffma2(u64& c, u64 a, u64 b) {
    asm("fma.rn.f32x2 %0, %1, %2, %0;" : "+l"(c) : "l"(a), "l"(b));
}

// ---------------------------------------------------------------------------
// K1: attention. 256 threads, 8 warps; one warp = one batch.
// Static smem only: x staging 8x768 (24KB) + W chunk 8x384 (12KB) + bias.
// W streamed through smem in 16 chunks of 8 k-rows.
// Lane l = head-dim d. Column mapping: col = jj*32 + l, jj = 3h{Q},3h+1{K},3h+2{V}.
// ---------------------------------------------------------------------------
__global__ void __launch_bounds__(256) k_attn(
    const float* __restrict__ x,
    const float* __restrict__ W0, const float* __restrict__ b0,
    const float* __restrict__ W1, const float* __restrict__ b1,
    const float* __restrict__ W2, const float* __restrict__ b2,
    const float* __restrict__ W3, const float* __restrict__ b3)
{
    __shared__ __align__(16) float xsm[8][768];   // 24576 B
    __shared__ __align__(16) float Wc[8][384];    // 12288 B
    __shared__ float bsm[384];                    //  1536 B

    const int tid  = threadIdx.x;
    const int w    = tid >> 5;
    const int lane = tid & 31;
    const int b    = blockIdx.x * 8 + w;

    // bias to smem
    for (int idx = tid; idx < 384; idx += 256) {
        int h = idx / 96, cc = idx - h * 96;
        const float* bh = (h == 0) ? b0 : (h == 1) ? b1 : (h == 2) ? b2 : b3;
        bsm[idx] = bh[cc];
    }

    // stage this warp's batch: x[b] is 6x128 = 768 floats
    float* xw = xsm[w];
#pragma unroll
    for (int i = 0; i < 24; ++i)
        xw[lane + 32 * i] = x[(size_t)b * 768 + lane + 32 * i];

    __syncthreads();   // bsm + xsm visible

    // qkv accumulators: pairs over s: acc[p][jj] = (s=2p, s=2p+1)
    u64 acc[3][12];
#pragma unroll
    for (int p = 0; p < 3; ++p)
#pragma unroll
        for (int jj = 0; jj < 12; ++jj) {
            float bc = bsm[jj * 32 + lane];
            acc[p][jj] = pk2(bc, bc);
        }

    // stream W through smem: 16 chunks x 8 k-rows
    for (int c = 0; c < 16; ++c) {
        __syncthreads();   // previous chunk's compute done
#pragma unroll
        for (int h = 0; h < 4; ++h) {
            const float* Wh = (h == 0) ? W0 : (h == 1) ? W1 : (h == 2) ? W2 : W3;
            for (int idx = tid; idx < 768; idx += 256) {
                int kr = idx / 96, cc = idx - kr * 96;
                Wc[kr][h * 96 + cc] = Wh[(c * 8 + kr) * 96 + cc];
            }
        }
        __syncthreads();   // chunk visible

#pragma unroll
        for (int kk = 0; kk < 8; ++kk) {
            const int k = c * 8 + kk;
            u64 xp0 = pk2(xw[k],       xw[128 + k]);
            u64 xp1 = pk2(xw[256 + k], xw[384 + k]);
            u64 xp2 = pk2(xw[512 + k], xw[640 + k]);
            const float* wr = &Wc[kk][lane];
#pragma unroll
            for (int jj = 0; jj < 12; ++jj) {
                float wv = wr[jj * 32];
                u64 wp = pk2(wv, wv);
                ffma2(acc[0][jj], xp0, wp);
                ffma2(acc[1][jj], xp1, wp);
                ffma2(acc[2][jj], xp2, wp);
            }
        }
    }

    float qv[6][12];
#pragma unroll
    for (int p = 0; p < 3; ++p)
#pragma unroll
        for (int jj = 0; jj < 12; ++jj)
            upk2(acc[p][jj], qv[2 * p][jj], qv[2 * p + 1][jj]);

    // m-stats partials: x part
    float ssum[6], ssq[6];
#pragma unroll
    for (int s = 0; s < 6; ++s) {
        float a = 0.f, q = 0.f;
#pragma unroll
        for (int i = 0; i < 4; ++i) {
            float v = xw[s * 128 + lane + 32 * i];
            a += v; q += v * v;
        }
        ssum[s] = a; ssq[s] = q;
    }

    // attention per head: scores = Q K^T (no softmax), out = scores V
#pragma unroll
    for (int h = 0; h < 4; ++h) {
#pragma unroll
        for (int qi = 0; qi < 6; ++qi) {
            float ao = 0.f;
#pragma unroll
            for (int ki = 0; ki < 6; ++ki) {
                float p = qv[qi][3 * h] * qv[ki][3 * h + 1];
#pragma unroll
                for (int off = 16; off > 0; off >>= 1)
                    p += __shfl_xor_sync(0xffffffffu, p, off);
                ao = fmaf(p, qv[ki][3 * h + 2], ao);
            }
            g_attn[((size_t)b * 6 + qi) * 128 + h * 32 + lane] = ao;
            ssum[qi] += ao;
            ssq[qi]  += ao * ao;
        }
    }

#pragma unroll
    for (int s = 0; s < 6; ++s) {
        float a = ssum[s], q = ssq[s];
#pragma unroll
        for (int off = 16; off > 0; off >>= 1) {
            a += __shfl_xor_sync(0xffffffffu, a, off);
            q += __shfl_xor_sync(0xffffffffu, q, off);
        }
        if (lane == 0) {
            g_msum[b * 6 + s]   = a;
            g_msumsq[b * 6 + s] = q;
        }
    }
}

// ---------------------------------------------------------------------------
// K2: n = LN1(m) @ Wf + bf. M=393216, K=256, N=256. BM=128, BN=256, BK=16,
// 512 threads, 8x8 micro-tile (FFMA2). LN transform applied on A-tile load.
// ---------------------------------------------------------------------------
__global__ void __launch_bounds__(512) k_ln1_wf(
    const float* __restrict__ x,
    const float* __restrict__ g1, const float* __restrict__ be1,
    const float* __restrict__ Wf, const float* __restrict__ bf)
{
    __shared__ __align__(16) float Asm[16][132];
    __shared__ __align__(16) float Bsm[16][256];
    __shared__ float mu1s[128], rs1s[128], g1s[256], be1s[256];

    const int tid = threadIdx.x;
    const int row0 = blockIdx.x * 128;

    if (tid < 128) {
        float ms = g_msum[row0 + tid], mq = g_msumsq[row0 + tid];
        float mu = ms * (1.f / 256.f);
        float var = mq * (1.f / 256.f) - mu * mu;
        mu1s[tid] = mu;
        rs1s[tid] = rsqrtf(var + EPS_LN);
    }
    if (tid < 256) { g1s[tid] = g1[tid]; be1s[tid] = be1[tid]; }

    const int tr = tid >> 5, tc = tid & 31;
    const int am = tid >> 2, ac = tid & 3;
    const int bk = tid >> 5, bn = (tid & 31) * 8;

    u64 c[2][4][2][2];
#pragma unroll
    for (int a = 0; a < 2; ++a)
#pragma unroll
        for (int i = 0; i < 4; ++i)
#pragma unroll
            for (int ch = 0; ch < 2; ++ch) { c[a][i][ch][0] = 0ull; c[a][i][ch][1] = 0ull; }

    __syncthreads();

    for (int kb = 0; kb < 256; kb += 16) {
        const float* asrc = (kb < 128)
            ? x      + (size_t)(row0 + am) * 128 + kb + ac * 4
            : g_attn + (size_t)(row0 + am) * 128 + (kb - 128) + ac * 4;
        float4 av = *(const float4*)asrc;
        const float4* bp = (const float4*)(Wf + (size_t)(kb + bk) * 256 + bn);
        float4 bv0 = bp[0], bv1 = bp[1];

        __syncthreads();
        {
            float mu = mu1s[am], rs = rs1s[am];
            float va[4] = {av.x, av.y, av.z, av.w};
#pragma unroll
            for (int i = 0; i < 4; ++i) {
                int kg = kb + ac * 4 + i;
                Asm[ac * 4 + i][am] = fmaf((va[i] - mu) * rs, g1s[kg], be1s[kg]);
            }
            *(float4*)&Bsm[bk][bn]     = bv0;
            *(float4*)&Bsm[bk][bn + 4] = bv1;
        }
        __syncthreads();

#pragma unroll
        for (int k = 0; k < 16; ++k) {
            float4 a0 = *(const float4*)&Asm[k][tr * 4];
            float4 a1 = *(const float4*)&Asm[k][64 + tr * 4];
            float4 b0 = *(const float4*)&Bsm[k][tc * 4];
            float4 b1 = *(const float4*)&Bsm[k][128 + tc * 4];
            u64 bb00 = pk2(b0.x, b0.y), bb01 = pk2(b0.z, b0.w);
            u64 bb10 = pk2(b1.x, b1.y), bb11 = pk2(b1.z, b1.w);
            float ar[2][4] = {{a0.x, a0.y, a0.z, a0.w}, {a1.x, a1.y, a1.z, a1.w}};
#pragma unroll
            for (int rh = 0; rh < 2; ++rh)
#pragma unroll
                for (int i = 0; i < 4; ++i) {
                    u64 aa = pk2(ar[rh][i], ar[rh][i]);
                    ffma2(c[rh][i][0][0], aa, bb00);
                    ffma2(c[rh][i][0][1], aa, bb01);
                    ffma2(c[rh][i][1][0], aa, bb10);
                    ffma2(c[rh][i][1][1], aa, bb11);
                }
        }
    }

#pragma unroll
    for (int rh = 0; rh < 2; ++rh)
#pragma unroll
        for (int i = 0; i < 4; ++i) {
            int r = row0 + rh * 64 + tr * 4 + i;
#pragma unroll
            for (int ch = 0; ch < 2; ++ch) {
                int nb = ch * 128 + tc * 4;
                float v0, v1, v2, v3;
                upk2(c[rh][i][ch][0], v0, v1);
                upk2(c[rh][i][ch][1], v2, v3);
                float4 o;
                o.x = v0 + bf[nb + 0];
                o.y = v1 + bf[nb + 1];
                o.z = v2 + bf[nb + 2];
                o.w = v3 + bf[nb + 3];
                *(float4*)&g_n[(size_t)r * 256 + nb] = o;
            }
        }
}

// ---------------------------------------------------------------------------
// K2b: LN2 stats over concat(n, m) per row (512 dims). One warp per row.
// ---------------------------------------------------------------------------
__global__ void __launch_bounds__(256) k_stats2()
{
    const int w = threadIdx.x >> 5, lane = threadIdx.x & 31;
    const int r = blockIdx.x * 8 + w;
    const float4* p = (const float4*)(g_n + (size_t)r * 256);
    float4 a  = p[lane];
    float4 b2 = p[32 + lane];
    float s = a.x + a.y + a.z + a.w + b2.x + b2.y + b2.z + b2.w;
    float q = a.x * a.x + a.y * a.y + a.z * a.z + a.w * a.w
            + b2.x * b2.x + b2.y * b2.y + b2.z * b2.z + b2.w * b2.w;
#pragma unroll
    for (int off = 16; off > 0; off >>= 1) {
        s += __shfl_xor_sync(0xffffffffu, s, off);
        q += __shfl_xor_sync(0xffffffffu, q, off);
    }
    if (lane == 0) {
        float tot  = g_msum[r] + s;
        float totq = g_msumsq[r] + q;
        float mu  = tot * (1.f / 512.f);
        float var = totq * (1.f / 512.f) - mu * mu;
        g_mu2[r] = mu;
        g_rs2[r] = rsqrtf(var + EPS_LN);
    }
}

// ---------------------------------------------------------------------------
// K3: out = relu( LN2(concat(n,m)) @ Ws + bs ). M=65536, K=3072, N=256.
// BM=128 (batches), BN=256, BK=16, 512 threads, 8x8 micro-tile (FFMA2).
// A element (b, k): s = k>>9, j = k&511; j<256 -> n, j<384 -> x, else attn.
// ---------------------------------------------------------------------------
__global__ void __launch_bounds__(512) k_ln2_ws(
    const float* __restrict__ x,
    const float* __restrict__ g2, const float* __restrict__ be2,
    const float* __restrict__ Ws, const float* __restrict__ bs,
    float* __restrict__ out)
{
    __shared__ __align__(16) float Asm[16][132];
    __shared__ __align__(16) float Bsm[16][256];
    __shared__ float mu2s[768], rs2s[768], g2s[512], be2s[512];

    const int tid = threadIdx.x;
    const int b0 = blockIdx.x * 128;

    for (int idx = tid; idx < 768; idx += 512) {
        mu2s[idx] = g_mu2[b0 * 6 + idx];
        rs2s[idx] = g_rs2[b0 * 6 + idx];
    }
    if (tid < 512) { g2s[tid] = g2[tid]; be2s[tid] = be2[tid]; }

    const int tr = tid >> 5, tc = tid & 31;
    const int am = tid >> 2, ac = tid & 3;
    const int bk = tid >> 5, bn = (tid & 31) * 8;

    u64 c[2][4][2][2];
#pragma unroll
    for (int a = 0; a < 2; ++a)
#pragma unroll
        for (int i = 0; i < 4; ++i)
#pragma unroll
            for (int ch = 0; ch < 2; ++ch) { c[a][i][ch][0] = 0ull; c[a][i][ch][1] = 0ull; }

    __syncthreads();

    for (int kb = 0; kb < 3072; kb += 16) {
        const int s  = kb >> 9;
        const int j0 = kb & 511;
        const int b  = b0 + am;
        const float* asrc;
        if (j0 < 256)      asrc = g_n    + (size_t)(b * 6 + s) * 256 + j0 + ac * 4;
        else if (j0 < 384) asrc = x      + (size_t)(b * 6 + s) * 128 + (j0 - 256) + ac * 4;
        else               asrc = g_attn + (size_t)(b * 6 + s) * 128 + (j0 - 384) + ac * 4;
        float4 av = *(const float4*)asrc;
        const float4* bp = (const float4*)(Ws + (size_t)(kb + bk) * 256 + bn);
        float4 bv0 = bp[0], bv1 = bp[1];

        __syncthreads();
        {
            float mu = mu2s[am * 6 + s], rs = rs2s[am * 6 + s];
            float va[4] = {av.x, av.y, av.z, av.w};
#pragma unroll
            for (int i = 0; i < 4; ++i) {
                int jg = j0 + ac * 4 + i;
                Asm[ac * 4 + i][am] = fmaf((va[i] - mu) * rs, g2s[jg], be2s[jg]);
            }
            *(float4*)&Bsm[bk][bn]     = bv0;
            *(float4*)&Bsm[bk][bn + 4] = bv1;
        }
        __syncthreads();

#pragma unroll
        for (int k = 0; k < 16; ++k) {
            float4 a0 = *(const float4*)&Asm[k][tr * 4];
            float4 a1 = *(const float4*)&Asm[k][64 + tr * 4];
            float4 b0 = *(const float4*)&Bsm[k][tc * 4];
            float4 b1 = *(const float4*)&Bsm[k][128 + tc * 4];
            u64 bb00 = pk2(b0.x, b0.y), bb01 = pk2(b0.z, b0.w);
            u64 bb10 = pk2(b1.x, b1.y), bb11 = pk2(b1.z, b1.w);
            float ar[2][4] = {{a0.x, a0.y, a0.z, a0.w}, {a1.x, a1.y, a1.z, a1.w}};
#pragma unroll
            for (int rh = 0; rh < 2; ++rh)
#pragma unroll
                for (int i = 0; i < 4; ++i) {
                    u64 aa = pk2(ar[rh][i], ar[rh][i]);
                    ffma2(c[rh][i][0][0], aa, bb00);
                    ffma2(c[rh][i][0][1], aa, bb01);
                    ffma2(c[rh][i][1][0], aa, bb10);
                    ffma2(c[rh][i][1][1], aa, bb11);
                }
        }
    }

#pragma unroll
    for (int rh = 0; rh < 2; ++rh)
#pragma unroll
        for (int i = 0; i < 4; ++i) {
            int b = b0 + rh * 64 + tr * 4 + i;
#pragma unroll
            for (int ch = 0; ch < 2; ++ch) {
                int nb = ch * 128 + tc * 4;
                float v0, v1, v2, v3;
                upk2(c[rh][i][ch][0], v0, v1);
                upk2(c[rh][i][ch][1], v2, v3);
                float4 o;
                o.x = fmaxf(v0 + bs[nb + 0], 0.f);
                o.y = fmaxf(v1 + bs[nb + 1], 0.f);
                o.z = fmaxf(v2 + bs[nb + 2], 0.f);
                o.w = fmaxf(v3 + bs[nb + 3], 0.f);
                *(float4*)&out[(size_t)b * 256 + nb] = o;
            }
        }
}

// ---------------------------------------------------------------------------
// kernel_launch: PURE kernel launches only. No cudaFuncSetAttribute, no
// dynamic smem, no host API calls — fully graph-capture-safe.
// ---------------------------------------------------------------------------
extern "C" void kernel_launch(void* const* d_in, const int* in_sizes, int n_in,
                              void* d_out, int out_size)
{
    (void)in_sizes; (void)n_in; (void)out_size;
    const float* x   = (const float*)d_in[0];
    const float* W0  = (const float*)d_in[1];
    const float* b0  = (const float*)d_in[2];
    const float* W1  = (const float*)d_in[3];
    const float* b1  = (const float*)d_in[4];
    const float* W2  = (const float*)d_in[5];
    const float* b2  = (const float*)d_in[6];
    const float* W3  = (const float*)d_in[7];
    const float* b3  = (const float*)d_in[8];
    const float* g1  = (const float*)d_in[9];
    const float* be1 = (const float*)d_in[10];
    const float* Wf  = (const float*)d_in[11];
    const float* bf  = (const float*)d_in[12];
    const float* g2  = (const float*)d_in[13];
    const float* be2 = (const float*)d_in[14];
    const float* Ws  = (const float*)d_in[15];
    const float* bs  = (const float*)d_in[16];
    float* out = (float*)d_out;

    k_attn<<<8192, 256>>>(x, W0, b0, W1, b1, W2, b2, W3, b3);
    k_ln1_wf<<<3072, 512>>>(x, g1, be1, Wf, bf);
    k_stats2<<<49152, 256>>>();
    k_ln2_ws<<<512, 512>>>(x, g2, be2, Ws, bs, out);
}

// round 3
// speedup vs baseline: 1.0015x; 1.0015x over previous
#include <cuda_runtime.h>
#include <cuda_bf16.h>
#include <cstdint>

// ---------------------------------------------------------------------------
// MultiAttention fused pipeline, fp32 + FFMA2 (fma.rn.f32x2).
// Round 1: kernel_launch is PURE kernel launches (no host API calls — the
// Round-0 cudaFuncSetAttribute during graph capture is the suspected cause of
// replay divergence). k_attn restructured to <=48KB STATIC shared memory.
//
//   K1: per-batch qkv GEMM (x(6,128) @ Wcat(128,384) + bcat) + attention
//       (scores = Q K^T, out = scores V, no softmax) -> g_attn, plus
//       sum/sumsq of m = concat(x, attn) per (b,s) row -> g_msum/g_msumsq.
//   K2: n = LN1(m) @ Wf + bf.   LN applied during A-tile load.
//   K2b: LN2 stats over concat(n, m) (512 dims) -> g_mu2/g_rs2.
//   K3: out = relu( LN2(concat(n,m)) @ Ws + bs ), K=3072, N=256.
// ---------------------------------------------------------------------------

#define BATCH   65536
#define ROWS6   (BATCH * 6)          // 393216
#define EPS_LN  1e-5f

// Scratch (device globals: allocation-free rule)
__device__ __align__(16) float g_attn[ROWS6 * 128];   // 201 MB
__device__ __align__(16) float g_n[ROWS6 * 256];      // 403 MB
__device__ __align__(16) float g_msum[ROWS6];
__device__ __align__(16) float g_msumsq[ROWS6];
__device__ __align__(16) float g_mu2[ROWS6];
__device__ __align__(16) float g_rs2[ROWS6];

typedef unsigned long long u64;

__device__ __forceinline__ u64 pk2(float x, float y) {
    u64 r;
    asm("mov.b64 %0, {%1, %2};" : "=l"(r) : "f"(x), "f"(y));
    return r;
}
__device__ __forceinline__ void upk2(u64 v, float& x, float& y) {
    asm("mov.b64 {%0, %1}, %2;" : "=f"(x), "=f"(y) : "l"(v));
}
// c = a*b + c (packed f32x2 -> SASS FFMA2, 2x fp32 rate)
__device__ __forceinline__ void ffma2(u64& c, u64 a, u64 b) {
    asm("fma.rn.f32x2 %0, %1, %2, %0;" : "+l"(c) : "l"(a), "l"(b));
}

// ---------------------------------------------------------------------------
// K1: attention. 256 threads, 8 warps; one warp = one batch.
// Static smem only: x staging 8x768 (24KB) + W chunk 8x384 (12KB) + bias.
// W streamed through smem in 16 chunks of 8 k-rows.
// Lane l = head-dim d. Column mapping: col = jj*32 + l, jj = 3h{Q},3h+1{K},3h+2{V}.
// ---------------------------------------------------------------------------
__global__ void __launch_bounds__(256) k_attn(
    const float* __restrict__ x,
    const float* __restrict__ W0, const float* __restrict__ b0,
    const float* __restrict__ W1, const float* __restrict__ b1,
    const float* __restrict__ W2, const float* __restrict__ b2,
    const float* __restrict__ W3, const float* __restrict__ b3)
{
    __shared__ __align__(16) float xsm[8][768];   // 24576 B
    __shared__ __align__(16) float Wc[8][384];    // 12288 B
    __shared__ float bsm[384];                    //  1536 B

    const int tid  = threadIdx.x;
    const int w    = tid >> 5;
    const int lane = tid & 31;
    const int b    = blockIdx.x * 8 + w;

    // bias to smem
    for (int idx = tid; idx < 384; idx += 256) {
        int h = idx / 96, cc = idx - h * 96;
        const float* bh = (h == 0) ? b0 : (h == 1) ? b1 : (h == 2) ? b2 : b3;
        bsm[idx] = bh[cc];
    }

    // stage this warp's batch: x[b] is 6x128 = 768 floats
    float* xw = xsm[w];
#pragma unroll
    for (int i = 0; i < 24; ++i)
        xw[lane + 32 * i] = x[(size_t)b * 768 + lane + 32 * i];

    __syncthreads();   // bsm + xsm visible

    // qkv accumulators: pairs over s: acc[p][jj] = (s=2p, s=2p+1)
    u64 acc[3][12];
#pragma unroll
    for (int p = 0; p < 3; ++p)
#pragma unroll
        for (int jj = 0; jj < 12; ++jj) {
            float bc = bsm[jj * 32 + lane];
            acc[p][jj] = pk2(bc, bc);
        }

    // stream W through smem: 16 chunks x 8 k-rows
    for (int c = 0; c < 16; ++c) {
        __syncthreads();   // previous chunk's compute done
#pragma unroll
        for (int h = 0; h < 4; ++h) {
            const float* Wh = (h == 0) ? W0 : (h == 1) ? W1 : (h == 2) ? W2 : W3;
            for (int idx = tid; idx < 768; idx += 256) {
                int kr = idx / 96, cc = idx - kr * 96;
                Wc[kr][h * 96 + cc] = Wh[(c * 8 + kr) * 96 + cc];
            }
        }
        __syncthreads();   // chunk visible

#pragma unroll
        for (int kk = 0; kk < 8; ++kk) {
            const int k = c * 8 + kk;
            u64 xp0 = pk2(xw[k],       xw[128 + k]);
            u64 xp1 = pk2(xw[256 + k], xw[384 + k]);
            u64 xp2 = pk2(xw[512 + k], xw[640 + k]);
            const float* wr = &Wc[kk][lane];
#pragma unroll
            for (int jj = 0; jj < 12; ++jj) {
                float wv = wr[jj * 32];
                u64 wp = pk2(wv, wv);
                ffma2(acc[0][jj], xp0, wp);
                ffma2(acc[1][jj], xp1, wp);
                ffma2(acc[2][jj], xp2, wp);
            }
        }
    }

    float qv[6][12];
#pragma unroll
    for (int p = 0; p < 3; ++p)
#pragma unroll
        for (int jj = 0; jj < 12; ++jj)
            upk2(acc[p][jj], qv[2 * p][jj], qv[2 * p + 1][jj]);

    // m-stats partials: x part
    float ssum[6], ssq[6];
#pragma unroll
    for (int s = 0; s < 6; ++s) {
        float a = 0.f, q = 0.f;
#pragma unroll
        for (int i = 0; i < 4; ++i) {
            float v = xw[s * 128 + lane + 32 * i];
            a += v; q += v * v;
        }
        ssum[s] = a; ssq[s] = q;
    }

    // attention per head: scores = Q K^T (no softmax), out = scores V
#pragma unroll
    for (int h = 0; h < 4; ++h) {
#pragma unroll
        for (int qi = 0; qi < 6; ++qi) {
            float ao = 0.f;
#pragma unroll
            for (int ki = 0; ki < 6; ++ki) {
                float p = qv[qi][3 * h] * qv[ki][3 * h + 1];
#pragma unroll
                for (int off = 16; off > 0; off >>= 1)
                    p += __shfl_xor_sync(0xffffffffu, p, off);
                ao = fmaf(p, qv[ki][3 * h + 2], ao);
            }
            g_attn[((size_t)b * 6 + qi) * 128 + h * 32 + lane] = ao;
            ssum[qi] += ao;
            ssq[qi]  += ao * ao;
        }
    }

#pragma unroll
    for (int s = 0; s < 6; ++s) {
        float a = ssum[s], q = ssq[s];
#pragma unroll
        for (int off = 16; off > 0; off >>= 1) {
            a += __shfl_xor_sync(0xffffffffu, a, off);
            q += __shfl_xor_sync(0xffffffffu, q, off);
        }
        if (lane == 0) {
            g_msum[b * 6 + s]   = a;
            g_msumsq[b * 6 + s] = q;
        }
    }
}

// ---------------------------------------------------------------------------
// K2: n = LN1(m) @ Wf + bf. M=393216, K=256, N=256. BM=128, BN=256, BK=16,
// 512 threads, 8x8 micro-tile (FFMA2). LN transform applied on A-tile load.
// ---------------------------------------------------------------------------
__global__ void __launch_bounds__(512) k_ln1_wf(
    const float* __restrict__ x,
    const float* __restrict__ g1, const float* __restrict__ be1,
    const float* __restrict__ Wf, const float* __restrict__ bf)
{
    __shared__ __align__(16) float Asm[16][132];
    __shared__ __align__(16) float Bsm[16][256];
    __shared__ float mu1s[128], rs1s[128], g1s[256], be1s[256];

    const int tid = threadIdx.x;
    const int row0 = blockIdx.x * 128;

    if (tid < 128) {
        float ms = g_msum[row0 + tid], mq = g_msumsq[row0 + tid];
        float mu = ms * (1.f / 256.f);
        float var = mq * (1.f / 256.f) - mu * mu;
        mu1s[tid] = mu;
        rs1s[tid] = rsqrtf(var + EPS_LN);
    }
    if (tid < 256) { g1s[tid] = g1[tid]; be1s[tid] = be1[tid]; }

    const int tr = tid >> 5, tc = tid & 31;
    const int am = tid >> 2, ac = tid & 3;
    const int bk = tid >> 5, bn = (tid & 31) * 8;

    u64 c[2][4][2][2];
#pragma unroll
    for (int a = 0; a < 2; ++a)
#pragma unroll
        for (int i = 0; i < 4; ++i)
#pragma unroll
            for (int ch = 0; ch < 2; ++ch) { c[a][i][ch][0] = 0ull; c[a][i][ch][1] = 0ull; }

    __syncthreads();

    for (int kb = 0; kb < 256; kb += 16) {
        const float* asrc = (kb < 128)
            ? x      + (size_t)(row0 + am) * 128 + kb + ac * 4
            : g_attn + (size_t)(row0 + am) * 128 + (kb - 128) + ac * 4;
        float4 av = *(const float4*)asrc;
        const float4* bp = (const float4*)(Wf + (size_t)(kb + bk) * 256 + bn);
        float4 bv0 = bp[0], bv1 = bp[1];

        __syncthreads();
        {
            float mu = mu1s[am], rs = rs1s[am];
            float va[4] = {av.x, av.y, av.z, av.w};
#pragma unroll
            for (int i = 0; i < 4; ++i) {
                int kg = kb + ac * 4 + i;
                Asm[ac * 4 + i][am] = fmaf((va[i] - mu) * rs, g1s[kg], be1s[kg]);
            }
            *(float4*)&Bsm[bk][bn]     = bv0;
            *(float4*)&Bsm[bk][bn + 4] = bv1;
        }
        __syncthreads();

#pragma unroll
        for (int k = 0; k < 16; ++k) {
            float4 a0 = *(const float4*)&Asm[k][tr * 4];
            float4 a1 = *(const float4*)&Asm[k][64 + tr * 4];
            float4 b0 = *(const float4*)&Bsm[k][tc * 4];
            float4 b1 = *(const float4*)&Bsm[k][128 + tc * 4];
            u64 bb00 = pk2(b0.x, b0.y), bb01 = pk2(b0.z, b0.w);
            u64 bb10 = pk2(b1.x, b1.y), bb11 = pk2(b1.z, b1.w);
            float ar[2][4] = {{a0.x, a0.y, a0.z, a0.w}, {a1.x, a1.y, a1.z, a1.w}};
#pragma unroll
            for (int rh = 0; rh < 2; ++rh)
#pragma unroll
                for (int i = 0; i < 4; ++i) {
                    u64 aa = pk2(ar[rh][i], ar[rh][i]);
                    ffma2(c[rh][i][0][0], aa, bb00);
                    ffma2(c[rh][i][0][1], aa, bb01);
                    ffma2(c[rh][i][1][0], aa, bb10);
                    ffma2(c[rh][i][1][1], aa, bb11);
                }
        }
    }

#pragma unroll
    for (int rh = 0; rh < 2; ++rh)
#pragma unroll
        for (int i = 0; i < 4; ++i) {
            int r = row0 + rh * 64 + tr * 4 + i;
#pragma unroll
            for (int ch = 0; ch < 2; ++ch) {
                int nb = ch * 128 + tc * 4;
                float v0, v1, v2, v3;
                upk2(c[rh][i][ch][0], v0, v1);
                upk2(c[rh][i][ch][1], v2, v3);
                float4 o;
                o.x = v0 + bf[nb + 0];
                o.y = v1 + bf[nb + 1];
                o.z = v2 + bf[nb + 2];
                o.w = v3 + bf[nb + 3];
                *(float4*)&g_n[(size_t)r * 256 + nb] = o;
            }
        }
}

// ---------------------------------------------------------------------------
// K2b: LN2 stats over concat(n, m) per row (512 dims). One warp per row.
// ---------------------------------------------------------------------------
__global__ void __launch_bounds__(256) k_stats2()
{
    const int w = threadIdx.x >> 5, lane = threadIdx.x & 31;
    const int r = blockIdx.x * 8 + w;
    const float4* p = (const float4*)(g_n + (size_t)r * 256);
    float4 a  = p[lane];
    float4 b2 = p[32 + lane];
    float s = a.x + a.y + a.z + a.w + b2.x + b2.y + b2.z + b2.w;
    float q = a.x * a.x + a.y * a.y + a.z * a.z + a.w * a.w
            + b2.x * b2.x + b2.y * b2.y + b2.z * b2.z + b2.w * b2.w;
#pragma unroll
    for (int off = 16; off > 0; off >>= 1) {
        s += __shfl_xor_sync(0xffffffffu, s, off);
        q += __shfl_xor_sync(0xffffffffu, q, off);
    }
    if (lane == 0) {
        float tot  = g_msum[r] + s;
        float totq = g_msumsq[r] + q;
        float mu  = tot * (1.f / 512.f);
        float var = totq * (1.f / 512.f) - mu * mu;
        g_mu2[r] = mu;
        g_rs2[r] = rsqrtf(var + EPS_LN);
    }
}

// ---------------------------------------------------------------------------
// K3: out = relu( LN2(concat(n,m)) @ Ws + bs ). M=65536, K=3072, N=256.
// BM=128 (batches), BN=256, BK=16, 512 threads, 8x8 micro-tile (FFMA2).
// A element (b, k): s = k>>9, j = k&511; j<256 -> n, j<384 -> x, else attn.
// ---------------------------------------------------------------------------
__global__ void __launch_bounds__(512) k_ln2_ws(
    const float* __restrict__ x,
    const float* __restrict__ g2, const float* __restrict__ be2,
    const float* __restrict__ Ws, const float* __restrict__ bs,
    float* __restrict__ out)
{
    __shared__ __align__(16) float Asm[16][132];
    __shared__ __align__(16) float Bsm[16][256];
    __shared__ float mu2s[768], rs2s[768], g2s[512], be2s[512];

    const int tid = threadIdx.x;
    const int b0 = blockIdx.x * 128;

    for (int idx = tid; idx < 768; idx += 512) {
        mu2s[idx] = g_mu2[b0 * 6 + idx];
        rs2s[idx] = g_rs2[b0 * 6 + idx];
    }
    if (tid < 512) { g2s[tid] = g2[tid]; be2s[tid] = be2[tid]; }

    const int tr = tid >> 5, tc = tid & 31;
    const int am = tid >> 2, ac = tid & 3;
    const int bk = tid >> 5, bn = (tid & 31) * 8;

    u64 c[2][4][2][2];
#pragma unroll
    for (int a = 0; a < 2; ++a)
#pragma unroll
        for (int i = 0; i < 4; ++i)
#pragma unroll
            for (int ch = 0; ch < 2; ++ch) { c[a][i][ch][0] = 0ull; c[a][i][ch][1] = 0ull; }

    __syncthreads();

    for (int kb = 0; kb < 3072; kb += 16) {
        const int s  = kb >> 9;
        const int j0 = kb & 511;
        const int b  = b0 + am;
        const float* asrc;
        if (j0 < 256)      asrc = g_n    + (size_t)(b * 6 + s) * 256 + j0 + ac * 4;
        else if (j0 < 384) asrc = x      + (size_t)(b * 6 + s) * 128 + (j0 - 256) + ac * 4;
        else               asrc = g_attn + (size_t)(b * 6 + s) * 128 + (j0 - 384) + ac * 4;
        float4 av = *(const float4*)asrc;
        const float4* bp = (const float4*)(Ws + (size_t)(kb + bk) * 256 + bn);
        float4 bv0 = bp[0], bv1 = bp[1];

        __syncthreads();
        {
            float mu = mu2s[am * 6 + s], rs = rs2s[am * 6 + s];
            float va[4] = {av.x, av.y, av.z, av.w};
#pragma unroll
            for (int i = 0; i < 4; ++i) {
                int jg = j0 + ac * 4 + i;
                Asm[ac * 4 + i][am] = fmaf((va[i] - mu) * rs, g2s[jg], be2s[jg]);
            }
            *(float4*)&Bsm[bk][bn]     = bv0;
            *(float4*)&Bsm[bk][bn + 4] = bv1;
        }
        __syncthreads();

#pragma unroll
        for (int k = 0; k < 16; ++k) {
            float4 a0 = *(const float4*)&Asm[k][tr * 4];
            float4 a1 = *(const float4*)&Asm[k][64 + tr * 4];
            float4 b0 = *(const float4*)&Bsm[k][tc * 4];
            float4 b1 = *(const float4*)&Bsm[k][128 + tc * 4];
            u64 bb00 = pk2(b0.x, b0.y), bb01 = pk2(b0.z, b0.w);
            u64 bb10 = pk2(b1.x, b1.y), bb11 = pk2(b1.z, b1.w);
            float ar[2][4] = {{a0.x, a0.y, a0.z, a0.w}, {a1.x, a1.y, a1.z, a1.w}};
#pragma unroll
            for (int rh = 0; rh < 2; ++rh)
#pragma unroll
                for (int i = 0; i < 4; ++i) {
                    u64 aa = pk2(ar[rh][i], ar[rh][i]);
                    ffma2(c[rh][i][0][0], aa, bb00);
                    ffma2(c[rh][i][0][1], aa, bb01);
                    ffma2(c[rh][i][1][0], aa, bb10);
                    ffma2(c[rh][i][1][1], aa, bb11);
                }
        }
    }

#pragma unroll
    for (int rh = 0; rh < 2; ++rh)
#pragma unroll
        for (int i = 0; i < 4; ++i) {
            int b = b0 + rh * 64 + tr * 4 + i;
#pragma unroll
            for (int ch = 0; ch < 2; ++ch) {
                int nb = ch * 128 + tc * 4;
                float v0, v1, v2, v3;
                upk2(c[rh][i][ch][0], v0, v1);
                upk2(c[rh][i][ch][1], v2, v3);
                float4 o;
                o.x = fmaxf(v0 + bs[nb + 0], 0.f);
                o.y = fmaxf(v1 + bs[nb + 1], 0.f);
                o.z = fmaxf(v2 + bs[nb + 2], 0.f);
                o.w = fmaxf(v3 + bs[nb + 3], 0.f);
                *(float4*)&out[(size_t)b * 256 + nb] = o;
            }
        }
}

// ---------------------------------------------------------------------------
// kernel_launch: PURE kernel launches only. No cudaFuncSetAttribute, no
// dynamic smem, no host API calls — fully graph-capture-safe.
// ---------------------------------------------------------------------------
extern "C" void kernel_launch(void* const* d_in, const int* in_sizes, int n_in,
                              void* d_out, int out_size)
{
    (void)in_sizes; (void)n_in; (void)out_size;
    const float* x   = (const float*)d_in[0];
    const float* W0  = (const float*)d_in[1];
    const float* b0  = (const float*)d_in[2];
    const float* W1  = (const float*)d_in[3];
    const float* b1  = (const float*)d_in[4];
    const float* W2  = (const float*)d_in[5];
    const float* b2  = (const float*)d_in[6];
    const float* W3  = (const float*)d_in[7];
    const float* b3  = (const float*)d_in[8];
    const float* g1  = (const float*)d_in[9];
    const float* be1 = (const float*)d_in[10];
    const float* Wf  = (const float*)d_in[11];
    const float* bf  = (const float*)d_in[12];
    const float* g2  = (const float*)d_in[13];
    const float* be2 = (const float*)d_in[14];
    const float* Ws  = (const float*)d_in[15];
    const float* bs  = (const float*)d_in[16];
    float* out = (float*)d_out;

    k_attn<<<8192, 256>>>(x, W0, b0, W1, b1, W2, b2, W3, b3);
    k_ln1_wf<<<3072, 512>>>(x, g1, be1, Wf, bf);
    k_stats2<<<49152, 256>>>();
    k_ln2_ws<<<512, 512>>>(x, g2, be2, Ws, bs, out);
}

// round 9
// speedup vs baseline: 1.8665x; 1.8637x over previous
#include <cuda_runtime.h>
#include <cuda_bf16.h>
#include <cstdint>

#define ROWS6 393216
#define EPS_LN 1e-5f

// ---------------- scratch globals (allocation-free rule) -------------------
__device__ __align__(16) float g_qkv[(size_t)ROWS6 * 384];
__device__ __align__(16) float g_attn[(size_t)ROWS6 * 128];
__device__ __align__(16) float g_n[(size_t)ROWS6 * 256];
__device__ __align__(16) __nv_bfloat16 g_WcT_hi[384 * 128], g_WcT_lo[384 * 128];
__device__ __align__(16) __nv_bfloat16 g_WfT_hi[256 * 256], g_WfT_lo[256 * 256];
__device__ __align__(16) __nv_bfloat16 g_WsT_hi[256 * 3072], g_WsT_lo[256 * 3072];
__device__ float g_bc[384];
__device__ float g_msum[ROWS6], g_msumsq[ROWS6];
__device__ float g_mu1[ROWS6], g_rs1[ROWS6], g_mu2[ROWS6], g_rs2[ROWS6];

// ---------------- helpers --------------------------------------------------
__device__ __forceinline__ uint32_t smem_u32(const void* p) {
    uint32_t a;
    asm("{ .reg .u64 t; cvta.to.shared.u64 t, %1; cvt.u32.u64 %0, t; }" : "=r"(a) : "l"(p));
    return a;
}
__device__ __forceinline__ void ldsm4(uint32_t& r0, uint32_t& r1, uint32_t& r2, uint32_t& r3,
                                      uint32_t addr) {
    asm volatile("ldmatrix.sync.aligned.m8n8.x4.shared.b16 {%0,%1,%2,%3}, [%4];"
                 : "=r"(r0), "=r"(r1), "=r"(r2), "=r"(r3) : "r"(addr));
}
__device__ __forceinline__ void mma16816(float* d, const uint32_t* a, const uint32_t* b) {
    asm volatile("mma.sync.aligned.m16n8k16.row.col.f32.bf16.bf16.f32 "
                 "{%0,%1,%2,%3}, {%4,%5,%6,%7}, {%8,%9}, {%0,%1,%2,%3};"
                 : "+f"(d[0]), "+f"(d[1]), "+f"(d[2]), "+f"(d[3])
                 : "r"(a[0]), "r"(a[1]), "r"(a[2]), "r"(a[3]), "r"(b[0]), "r"(b[1]));
}

// ---------------------------------------------------------------------------
// GEMM tile driver: 256 thr, BM=128 x BN=128, BK=32, bf16 3-term split HMMA.
// A from aload (fp32 -> hi/lo bf16), B from prepped K-major hi/lo bf16.
// smem rows padded to 40 bf16 (80B) -> conflict-free ldmatrix, 16B aligned.
// ---------------------------------------------------------------------------
template <class ALoad, class Epi>
__device__ __forceinline__ void gemm_tile(
    const __nv_bfloat16* __restrict__ BhT, const __nv_bfloat16* __restrict__ BlT,
    int n0, int ktot, int nchunk, ALoad aload, Epi epi)
{
    __shared__ __align__(16) __nv_bfloat16 sA[2][128][40];   // 20480 B
    __shared__ __align__(16) __nv_bfloat16 sB[2][128][40];   // 20480 B

    const int tid = threadIdx.x;
    const int lane = tid & 31, wid = tid >> 5;
    const int m_base = (wid & 1) * 64, n_base = (wid >> 1) * 32;
    const int arow = lane & 15, acol = (lane >> 4) * 8;

    const uint32_t sAu = smem_u32(&sA[0][0][0]);
    const uint32_t sBu = smem_u32(&sB[0][0][0]);

    // load-thread mapping: 2 threads per row, 16 k each
    const int lrow = tid >> 1, lkh = (tid & 1) * 16;

    float d[4][4][4];
#pragma unroll
    for (int mi = 0; mi < 4; ++mi)
#pragma unroll
        for (int ni = 0; ni < 4; ++ni)
#pragma unroll
            for (int e = 0; e < 4; ++e) d[mi][ni][e] = 0.f;

    // prefetch chunk 0
    float av[16];
    uint4 pbh0, pbh1, pbl0, pbl1;
    aload(lrow, lkh, av);
    {
        const uint4* ph = (const uint4*)(BhT + (size_t)(n0 + lrow) * ktot + lkh);
        const uint4* pl = (const uint4*)(BlT + (size_t)(n0 + lrow) * ktot + lkh);
        pbh0 = ph[0]; pbh1 = ph[1]; pbl0 = pl[0]; pbl1 = pl[1];
    }

    for (int c = 0; c < nchunk; ++c) {
        // ---- store prefetched chunk to smem ----
        {
            uint32_t hi[8], lo[8];
#pragma unroll
            for (int i = 0; i < 8; ++i) {
                float a0 = av[2 * i], a1 = av[2 * i + 1];
                __nv_bfloat16 h0 = __float2bfloat16(a0), h1 = __float2bfloat16(a1);
                float l0 = a0 - __bfloat162float(h0), l1 = a1 - __bfloat162float(h1);
                __nv_bfloat162 hp = __halves2bfloat162(h0, h1);
                __nv_bfloat162 lp = __halves2bfloat162(__float2bfloat16(l0), __float2bfloat16(l1));
                hi[i] = *(uint32_t*)&hp;
                lo[i] = *(uint32_t*)&lp;
            }
            uint4* ah4 = (uint4*)&sA[0][lrow][lkh];
            uint4* al4 = (uint4*)&sA[1][lrow][lkh];
            ah4[0] = make_uint4(hi[0], hi[1], hi[2], hi[3]);
            ah4[1] = make_uint4(hi[4], hi[5], hi[6], hi[7]);
            al4[0] = make_uint4(lo[0], lo[1], lo[2], lo[3]);
            al4[1] = make_uint4(lo[4], lo[5], lo[6], lo[7]);
            uint4* bh4 = (uint4*)&sB[0][lrow][lkh];
            uint4* bl4 = (uint4*)&sB[1][lrow][lkh];
            bh4[0] = pbh0; bh4[1] = pbh1;
            bl4[0] = pbl0; bl4[1] = pbl1;
        }
        __syncthreads();

        // ---- prefetch next chunk (global -> regs), hidden under MMAs ----
        if (c + 1 < nchunk) {
            const int kb = (c + 1) * 32;
            aload(lrow, kb + lkh, av);
            const uint4* ph = (const uint4*)(BhT + (size_t)(n0 + lrow) * ktot + kb + lkh);
            const uint4* pl = (const uint4*)(BlT + (size_t)(n0 + lrow) * ktot + kb + lkh);
            pbh0 = ph[0]; pbh1 = ph[1]; pbl0 = pl[0]; pbl1 = pl[1];
        }

        // ---- MMA over the chunk in smem ----
#pragma unroll
        for (int kk = 0; kk < 32; kk += 16) {
            uint32_t ah[4][4], al[4][4];
#pragma unroll
            for (int mi = 0; mi < 4; ++mi) {
                const uint32_t off = (uint32_t)((m_base + mi * 16 + arow) * 40 + kk + acol) * 2;
                ldsm4(ah[mi][0], ah[mi][1], ah[mi][2], ah[mi][3], sAu + off);
                ldsm4(al[mi][0], al[mi][1], al[mi][2], al[mi][3], sAu + 10240 + off);
            }
            uint32_t bh[4][2], bl[4][2];
#pragma unroll
            for (int nt = 0; nt < 2; ++nt) {
                const uint32_t off = (uint32_t)((n_base + nt * 16 + arow) * 40 + kk + acol) * 2;
                uint32_t r0, r1, r2, r3;
                ldsm4(r0, r1, r2, r3, sBu + off);
                bh[2 * nt][0] = r0; bh[2 * nt][1] = r2;
                bh[2 * nt + 1][0] = r1; bh[2 * nt + 1][1] = r3;
                ldsm4(r0, r1, r2, r3, sBu + 10240 + off);
                bl[2 * nt][0] = r0; bl[2 * nt][1] = r2;
                bl[2 * nt + 1][0] = r1; bl[2 * nt + 1][1] = r3;
            }
#pragma unroll
            for (int mi = 0; mi < 4; ++mi)
#pragma unroll
                for (int ni = 0; ni < 4; ++ni) {
                    mma16816(d[mi][ni], ah[mi], bh[ni]);
                    mma16816(d[mi][ni], ah[mi], bl[ni]);
                    mma16816(d[mi][ni], al[mi], bh[ni]);
                }
        }
        __syncthreads();
    }

    // ---- epilogue: fragment -> epi(row, col, v0, v1) ----
#pragma unroll
    for (int mi = 0; mi < 4; ++mi)
#pragma unroll
        for (int ni = 0; ni < 4; ++ni) {
            const int r0 = m_base + mi * 16 + (lane >> 2);
            const int col = n_base + ni * 8 + 2 * (lane & 3);
            epi(r0, col, d[mi][ni][0], d[mi][ni][1]);
            epi(r0 + 8, col, d[mi][ni][2], d[mi][ni][3]);
        }
}

// ---------------------------------------------------------------------------
// k_prep: split weights to K-major bf16 hi/lo; concat qkv bias.
// ---------------------------------------------------------------------------
__global__ void __launch_bounds__(256) k_prep(
    const float* __restrict__ W0, const float* __restrict__ W1,
    const float* __restrict__ W2, const float* __restrict__ W3,
    const float* __restrict__ b0, const float* __restrict__ b1,
    const float* __restrict__ b2, const float* __restrict__ b3,
    const float* __restrict__ Wf, const float* __restrict__ Ws)
{
    const int i = blockIdx.x * 256 + threadIdx.x;
    if (i < 49152) {                       // WcT [384 n][128 k]
        int n = i >> 7, k = i & 127;
        int h = n / 96, cc = n - h * 96;
        const float* Wh = (h == 0) ? W0 : (h == 1) ? W1 : (h == 2) ? W2 : W3;
        float v = Wh[k * 96 + cc];
        __nv_bfloat16 hi = __float2bfloat16(v);
        g_WcT_hi[i] = hi;
        g_WcT_lo[i] = __float2bfloat16(v - __bfloat162float(hi));
    }
    if (i < 384) {
        int h = i / 96, cc = i - h * 96;
        g_bc[i] = ((h == 0) ? b0 : (h == 1) ? b1 : (h == 2) ? b2 : b3)[cc];
    }
    if (i < 65536) {                       // WfT [256 n][256 k]
        int n = i >> 8, k = i & 255;
        float v = Wf[(size_t)k * 256 + n];
        __nv_bfloat16 hi = __float2bfloat16(v);
        g_WfT_hi[i] = hi;
        g_WfT_lo[i] = __float2bfloat16(v - __bfloat162float(hi));
    }
    if (i < 786432) {                      // WsT [256 n][3072 k]
        int n = i / 3072, k = i - n * 3072;
        float v = Ws[(size_t)k * 256 + n];
        __nv_bfloat16 hi = __float2bfloat16(v);
        g_WsT_hi[i] = hi;
        g_WsT_lo[i] = __float2bfloat16(v - __bfloat162float(hi));
    }
}

// ---------------------------------------------------------------------------
// k_qkv: g_qkv = x @ Wcat + bcat.  M=393216, K=128, N=384 (grid.y tiles).
// ---------------------------------------------------------------------------
__global__ void __launch_bounds__(256) k_qkv(const float* __restrict__ x)
{
    const int row0 = blockIdx.x * 128, n0 = blockIdx.y * 128;
    gemm_tile(g_WcT_hi, g_WcT_lo, n0, 128, 4,
        [&](int row, int k0, float* a) {
            const float4* s = (const float4*)(x + (size_t)(row0 + row) * 128 + k0);
#pragma unroll
            for (int i = 0; i < 4; ++i) {
                float4 v = s[i];
                a[4 * i] = v.x; a[4 * i + 1] = v.y; a[4 * i + 2] = v.z; a[4 * i + 3] = v.w;
            }
        },
        [&](int row, int col, float v0, float v1) {
            float2 t;
            t.x = v0 + g_bc[n0 + col];
            t.y = v1 + g_bc[n0 + col + 1];
            *(float2*)(g_qkv + (size_t)(row0 + row) * 384 + n0 + col) = t;
        });
}

// ---------------------------------------------------------------------------
// k_attn2: per-batch attention from g_qkv + m stats (+ LN1 mu/rs).
// ---------------------------------------------------------------------------
__global__ void __launch_bounds__(256) k_attn2(const float* __restrict__ x)
{
    const int tid = threadIdx.x, w = tid >> 5, lane = tid & 31;
    const int b = blockIdx.x * 8 + w;

    float qv[6][12];
#pragma unroll
    for (int s = 0; s < 6; ++s)
#pragma unroll
        for (int jj = 0; jj < 12; ++jj)
            qv[s][jj] = g_qkv[((size_t)b * 6 + s) * 384 + jj * 32 + lane];

    float ssum[6], ssq[6];
#pragma unroll
    for (int s = 0; s < 6; ++s) {
        float a = 0.f, q = 0.f;
#pragma unroll
        for (int i = 0; i < 4; ++i) {
            float v = x[(size_t)b * 768 + s * 128 + lane + 32 * i];
            a += v; q += v * v;
        }
        ssum[s] = a; ssq[s] = q;
    }

#pragma unroll
    for (int h = 0; h < 4; ++h) {
#pragma unroll
        for (int qi = 0; qi < 6; ++qi) {
            float ao = 0.f;
#pragma unroll
            for (int ki = 0; ki < 6; ++ki) {
                float p = qv[qi][3 * h] * qv[ki][3 * h + 1];
#pragma unroll
                for (int off = 16; off > 0; off >>= 1)
                    p += __shfl_xor_sync(0xffffffffu, p, off);
                ao = fmaf(p, qv[ki][3 * h + 2], ao);
            }
            g_attn[((size_t)b * 6 + qi) * 128 + h * 32 + lane] = ao;
            ssum[qi] += ao;
            ssq[qi] += ao * ao;
        }
    }

#pragma unroll
    for (int s = 0; s < 6; ++s) {
        float a = ssum[s], q = ssq[s];
#pragma unroll
        for (int off = 16; off > 0; off >>= 1) {
            a += __shfl_xor_sync(0xffffffffu, a, off);
            q += __shfl_xor_sync(0xffffffffu, q, off);
        }
        if (lane == 0) {
            const int r = b * 6 + s;
            g_msum[r] = a;
            g_msumsq[r] = q;
            float mu = a * (1.f / 256.f);
            float var = q * (1.f / 256.f) - mu * mu;
            g_mu1[r] = mu;
            g_rs1[r] = rsqrtf(var + EPS_LN);
        }
    }
}

// ---------------------------------------------------------------------------
// k_ln1: g_n = LN1(m) @ Wf + bf.  M=393216, K=256, N=256.
// ---------------------------------------------------------------------------
__global__ void __launch_bounds__(256) k_ln1(
    const float* __restrict__ x, const float* __restrict__ g1,
    const float* __restrict__ be1, const float* __restrict__ bf)
{
    const int row0 = blockIdx.x * 128, n0 = blockIdx.y * 128;
    gemm_tile(g_WfT_hi, g_WfT_lo, n0, 256, 8,
        [&](int row, int k0, float* a) {
            const int r = row0 + row;
            const float* src = (k0 < 128) ? x + (size_t)r * 128 + k0
                                          : g_attn + (size_t)r * 128 + (k0 - 128);
            const float mu = g_mu1[r], rs = g_rs1[r];
            const float4* s4 = (const float4*)src;
#pragma unroll
            for (int i = 0; i < 4; ++i) {
                float4 v = s4[i];
                const int kg = k0 + 4 * i;
                a[4 * i]     = fmaf((v.x - mu) * rs, g1[kg],     be1[kg]);
                a[4 * i + 1] = fmaf((v.y - mu) * rs, g1[kg + 1], be1[kg + 1]);
                a[4 * i + 2] = fmaf((v.z - mu) * rs, g1[kg + 2], be1[kg + 2]);
                a[4 * i + 3] = fmaf((v.w - mu) * rs, g1[kg + 3], be1[kg + 3]);
            }
        },
        [&](int row, int col, float v0, float v1) {
            float2 t;
            t.x = v0 + bf[n0 + col];
            t.y = v1 + bf[n0 + col + 1];
            *(float2*)(g_n + (size_t)(row0 + row) * 256 + n0 + col) = t;
        });
}

// ---------------------------------------------------------------------------
// k_stats2: LN2 stats over concat(n, m). One warp per row.
// ---------------------------------------------------------------------------
__global__ void __launch_bounds__(256) k_stats2()
{
    const int w = threadIdx.x >> 5, lane = threadIdx.x & 31;
    const int r = blockIdx.x * 8 + w;
    const float4* p = (const float4*)(g_n + (size_t)r * 256);
    float4 a = p[lane];
    float4 b2 = p[32 + lane];
    float s = a.x + a.y + a.z + a.w + b2.x + b2.y + b2.z + b2.w;
    float q = a.x * a.x + a.y * a.y + a.z * a.z + a.w * a.w
            + b2.x * b2.x + b2.y * b2.y + b2.z * b2.z + b2.w * b2.w;
#pragma unroll
    for (int off = 16; off > 0; off >>= 1) {
        s += __shfl_xor_sync(0xffffffffu, s, off);
        q += __shfl_xor_sync(0xffffffffu, q, off);
    }
    if (lane == 0) {
        float tot = g_msum[r] + s, totq = g_msumsq[r] + q;
        float mu = tot * (1.f / 512.f);
        float var = totq * (1.f / 512.f) - mu * mu;
        g_mu2[r] = mu;
        g_rs2[r] = rsqrtf(var + EPS_LN);
    }
}

// ---------------------------------------------------------------------------
// k_out: out = relu( LN2(concat(n,m)) @ Ws + bs ).  M=65536, K=3072, N=256.
// ---------------------------------------------------------------------------
__global__ void __launch_bounds__(256) k_out(
    const float* __restrict__ x, const float* __restrict__ g2,
    const float* __restrict__ be2, const float* __restrict__ bs,
    float* __restrict__ out)
{
    const int b0 = blockIdx.x * 128, n0 = blockIdx.y * 128;
    gemm_tile(g_WsT_hi, g_WsT_lo, n0, 3072, 96,
        [&](int row, int k0, float* a) {
            const int b = b0 + row;
            const int s = k0 >> 9, j0 = k0 & 511;
            const float* src;
            if (j0 < 256)      src = g_n + (size_t)(b * 6 + s) * 256 + j0;
            else if (j0 < 384) src = x + (size_t)(b * 6 + s) * 128 + (j0 - 256);
            else               src = g_attn + (size_t)(b * 6 + s) * 128 + (j0 - 384);
            const float mu = g_mu2[b * 6 + s], rs = g_rs2[b * 6 + s];
            const float4* s4 = (const float4*)src;
#pragma unroll
            for (int i = 0; i < 4; ++i) {
                float4 v = s4[i];
                const int jg = j0 + 4 * i;
                a[4 * i]     = fmaf((v.x - mu) * rs, g2[jg],     be2[jg]);
                a[4 * i + 1] = fmaf((v.y - mu) * rs, g2[jg + 1], be2[jg + 1]);
                a[4 * i + 2] = fmaf((v.z - mu) * rs, g2[jg + 2], be2[jg + 2]);
                a[4 * i + 3] = fmaf((v.w - mu) * rs, g2[jg + 3], be2[jg + 3]);
            }
        },
        [&](int row, int col, float v0, float v1) {
            float2 t;
            t.x = fmaxf(v0 + bs[n0 + col], 0.f);
            t.y = fmaxf(v1 + bs[n0 + col + 1], 0.f);
            *(float2*)(out + (size_t)(b0 + row) * 256 + n0 + col) = t;
        });
}

// ---------------------------------------------------------------------------
// kernel_launch: pure kernel launches (graph-capture-safe, no host API calls)
// ---------------------------------------------------------------------------
extern "C" void kernel_launch(void* const* d_in, const int* in_sizes, int n_in,
                              void* d_out, int out_size)
{
    (void)in_sizes; (void)n_in; (void)out_size;
    const float* x   = (const float*)d_in[0];
    const float* W0  = (const float*)d_in[1];
    const float* b0  = (const float*)d_in[2];
    const float* W1  = (const float*)d_in[3];
    const float* b1  = (const float*)d_in[4];
    const float* W2  = (const float*)d_in[5];
    const float* b2  = (const float*)d_in[6];
    const float* W3  = (const float*)d_in[7];
    const float* b3  = (const float*)d_in[8];
    const float* g1  = (const float*)d_in[9];
    const float* be1 = (const float*)d_in[10];
    const float* Wf  = (const float*)d_in[11];
    const float* bf  = (const float*)d_in[12];
    const float* g2  = (const float*)d_in[13];
    const float* be2 = (const float*)d_in[14];
    const float* Ws  = (const float*)d_in[15];
    const float* bs  = (const float*)d_in[16];
    float* out = (float*)d_out;

    k_prep<<<3072, 256>>>(W0, W1, W2, W3, b0, b1, b2, b3, Wf, Ws);
    k_qkv<<<dim3(3072, 3), 256>>>(x);
    k_attn2<<<8192, 256>>>(x);
    k_ln1<<<dim3(3072, 2), 256>>>(x, g1, be1, bf);
    k_stats2<<<49152, 256>>>();
    k_out<<<dim3(512, 2), 256>>>(x, g2, be2, bs, out);
}

// round 10
// speedup vs baseline: 2.3030x; 1.2338x over previous
#include <cuda_runtime.h>
#include <cuda_bf16.h>
#include <cstdint>

#define ROWS6 393216
#define BATCH 65536
#define EPS_LN 1e-5f

// ---------------- scratch globals (allocation-free rule) -------------------
__device__ __align__(16) float g_qkv[(size_t)ROWS6 * 384];
__device__ __align__(16) float g_attn[(size_t)ROWS6 * 128];
__device__ __align__(16) float g_n[(size_t)ROWS6 * 256];
__device__ __align__(16) __nv_bfloat16 g_xh[(size_t)ROWS6 * 128], g_xl[(size_t)ROWS6 * 128];
__device__ __align__(16) __nv_bfloat16 g_A1h[(size_t)ROWS6 * 256], g_A1l[(size_t)ROWS6 * 256];
__device__ __align__(16) __nv_bfloat16 g_A2h[(size_t)BATCH * 3072], g_A2l[(size_t)BATCH * 3072];
__device__ __align__(16) __nv_bfloat16 g_WcT_hi[384 * 128], g_WcT_lo[384 * 128];
__device__ __align__(16) __nv_bfloat16 g_WfT_hi[256 * 256], g_WfT_lo[256 * 256];
__device__ __align__(16) __nv_bfloat16 g_WsT_hi[256 * 3072], g_WsT_lo[256 * 3072];
__device__ float g_bc[384];
__device__ float g_msum[ROWS6], g_msumsq[ROWS6];

// ---------------- helpers --------------------------------------------------
__device__ __forceinline__ uint32_t smem_u32(const void* p) {
    uint32_t a;
    asm("{ .reg .u64 t; cvta.to.shared.u64 t, %1; cvt.u32.u64 %0, t; }" : "=r"(a) : "l"(p));
    return a;
}
__device__ __forceinline__ void ldsm4(uint32_t& r0, uint32_t& r1, uint32_t& r2, uint32_t& r3,
                                      uint32_t addr) {
    asm volatile("ldmatrix.sync.aligned.m8n8.x4.shared.b16 {%0,%1,%2,%3}, [%4];"
                 : "=r"(r0), "=r"(r1), "=r"(r2), "=r"(r3) : "r"(addr));
}
__device__ __forceinline__ void mma16816(float* d, const uint32_t* a, const uint32_t* b) {
    asm volatile("mma.sync.aligned.m16n8k16.row.col.f32.bf16.bf16.f32 "
                 "{%0,%1,%2,%3}, {%4,%5,%6,%7}, {%8,%9}, {%0,%1,%2,%3};"
                 : "+f"(d[0]), "+f"(d[1]), "+f"(d[2]), "+f"(d[3])
                 : "r"(a[0]), "r"(a[1]), "r"(a[2]), "r"(a[3]), "r"(b[0]), "r"(b[1]));
}
__device__ __forceinline__ void cpasync16(uint32_t dst, const void* src) {
    asm volatile("cp.async.cg.shared.global [%0], [%1], 16;" :: "r"(dst), "l"(src));
}
__device__ __forceinline__ void cpcommit() {
    asm volatile("cp.async.commit_group;" ::: "memory");
}
__device__ __forceinline__ void bf16split(float v, __nv_bfloat16& h, __nv_bfloat16& l) {
    h = __float2bfloat16(v);
    l = __float2bfloat16(v - __bfloat162float(h));
}

// ---------------------------------------------------------------------------
// GEMM driver: 256 thr, 2 CTAs/SM. BM=128 x BN=128, BK=16, 2-stage cp.async.
// A and B both pre-split bf16 hi/lo, K-major in global.
// 3-term split: D = ah*bh + ah*bl + al*bh.
// smem: [2 stages][4 bufs: Ah,Al,Bh,Bl][128 rows][24 bf16 pad] = 48KB exactly.
// ---------------------------------------------------------------------------
template <class Epi>
__device__ __forceinline__ void gemm_cp(
    const __nv_bfloat16* __restrict__ Ah, const __nv_bfloat16* __restrict__ Al, int row0,
    const __nv_bfloat16* __restrict__ Bh, const __nv_bfloat16* __restrict__ Bl, int n0,
    int ktot, int nchunk, Epi epi)
{
    __shared__ __align__(16) __nv_bfloat16 sm[2][4][128][24];

    const int tid = threadIdx.x, lane = tid & 31, wid = tid >> 5;
    const int m_base = (wid & 1) * 64, n_base = (wid >> 1) * 32;
    const int arow = lane & 15, acol = (lane >> 4) * 8;
    const int lrow = tid >> 1, lh = (tid & 1) * 8;

    const uint32_t s0 = smem_u32(&sm[0][0][0][0]);
    const __nv_bfloat16* gs0 = Ah + (size_t)(row0 + lrow) * ktot + lh;
    const __nv_bfloat16* gs1 = Al + (size_t)(row0 + lrow) * ktot + lh;
    const __nv_bfloat16* gs2 = Bh + (size_t)(n0 + lrow) * ktot + lh;
    const __nv_bfloat16* gs3 = Bl + (size_t)(n0 + lrow) * ktot + lh;
    const uint32_t dstb = s0 + (uint32_t)(lrow * 24 + lh) * 2;

    float d[4][4][4];
#pragma unroll
    for (int mi = 0; mi < 4; ++mi)
#pragma unroll
        for (int ni = 0; ni < 4; ++ni)
#pragma unroll
            for (int e = 0; e < 4; ++e) d[mi][ni][e] = 0.f;

    // prologue: stage 0 and 1
    {
        cpasync16(dstb,          gs0);
        cpasync16(dstb + 6144,   gs1);
        cpasync16(dstb + 12288,  gs2);
        cpasync16(dstb + 18432,  gs3);
        cpcommit();
        cpasync16(dstb + 24576,  gs0 + 16);
        cpasync16(dstb + 30720,  gs1 + 16);
        cpasync16(dstb + 36864,  gs2 + 16);
        cpasync16(dstb + 43008,  gs3 + 16);
        cpcommit();
    }

    for (int c = 0; c < nchunk; ++c) {
        if (c == nchunk - 1)
            asm volatile("cp.async.wait_group 0;" ::: "memory");
        else
            asm volatile("cp.async.wait_group 1;" ::: "memory");
        __syncthreads();

        const int st = c & 1;
        const uint32_t bAh = s0 + (uint32_t)(st * 4 + 0) * 6144;
        const uint32_t bAl = s0 + (uint32_t)(st * 4 + 1) * 6144;
        const uint32_t bBh = s0 + (uint32_t)(st * 4 + 2) * 6144;
        const uint32_t bBl = s0 + (uint32_t)(st * 4 + 3) * 6144;

        // B fragments (hi & lo)
        uint32_t bh_[4][2], bl_[4][2];
#pragma unroll
        for (int nt = 0; nt < 2; ++nt) {
            const uint32_t off = (uint32_t)((n_base + nt * 16 + arow) * 24 + acol) * 2;
            uint32_t r0, r1, r2, r3;
            ldsm4(r0, r1, r2, r3, bBh + off);
            bh_[2 * nt][0] = r0; bh_[2 * nt][1] = r2;
            bh_[2 * nt + 1][0] = r1; bh_[2 * nt + 1][1] = r3;
            ldsm4(r0, r1, r2, r3, bBl + off);
            bl_[2 * nt][0] = r0; bl_[2 * nt][1] = r2;
            bl_[2 * nt + 1][0] = r1; bl_[2 * nt + 1][1] = r3;
        }
        // A hi fragments: ah*bh + ah*bl
        uint32_t af[4][4];
#pragma unroll
        for (int mi = 0; mi < 4; ++mi) {
            const uint32_t off = (uint32_t)((m_base + mi * 16 + arow) * 24 + acol) * 2;
            ldsm4(af[mi][0], af[mi][1], af[mi][2], af[mi][3], bAh + off);
        }
#pragma unroll
        for (int mi = 0; mi < 4; ++mi)
#pragma unroll
            for (int ni = 0; ni < 4; ++ni) {
                mma16816(d[mi][ni], af[mi], bh_[ni]);
                mma16816(d[mi][ni], af[mi], bl_[ni]);
            }
        // A lo fragments (reuse regs): al*bh
#pragma unroll
        for (int mi = 0; mi < 4; ++mi) {
            const uint32_t off = (uint32_t)((m_base + mi * 16 + arow) * 24 + acol) * 2;
            ldsm4(af[mi][0], af[mi][1], af[mi][2], af[mi][3], bAl + off);
        }
#pragma unroll
        for (int mi = 0; mi < 4; ++mi)
#pragma unroll
            for (int ni = 0; ni < 4; ++ni)
                mma16816(d[mi][ni], af[mi], bh_[ni]);

        __syncthreads();   // stage st fully consumed
        if (c + 2 < nchunk) {
            const int kb = (c + 2) * 16;
            const uint32_t db = dstb + (uint32_t)(st * 4) * 6144;
            cpasync16(db,          gs0 + kb);
            cpasync16(db + 6144,   gs1 + kb);
            cpasync16(db + 12288,  gs2 + kb);
            cpasync16(db + 18432,  gs3 + kb);
            cpcommit();
        } else {
            cpcommit();   // keep group accounting uniform
        }
    }

    // epilogue
#pragma unroll
    for (int mi = 0; mi < 4; ++mi)
#pragma unroll
        for (int ni = 0; ni < 4; ++ni) {
            const int r0 = m_base + mi * 16 + (lane >> 2);
            const int col = n_base + ni * 8 + 2 * (lane & 3);
            epi(r0, col, d[mi][ni][0], d[mi][ni][1]);
            epi(r0 + 8, col, d[mi][ni][2], d[mi][ni][3]);
        }
}

// ---------------------------------------------------------------------------
// k_prep: split weights to K-major bf16 hi/lo; concat qkv bias.
// ---------------------------------------------------------------------------
__global__ void __launch_bounds__(256) k_prep(
    const float* __restrict__ W0, const float* __restrict__ W1,
    const float* __restrict__ W2, const float* __restrict__ W3,
    const float* __restrict__ b0, const float* __restrict__ b1,
    const float* __restrict__ b2, const float* __restrict__ b3,
    const float* __restrict__ Wf, const float* __restrict__ Ws)
{
    const int i = blockIdx.x * 256 + threadIdx.x;
    if (i < 49152) {                       // WcT [384 n][128 k]
        int n = i >> 7, k = i & 127;
        int h = n / 96, cc = n - h * 96;
        const float* Wh = (h == 0) ? W0 : (h == 1) ? W1 : (h == 2) ? W2 : W3;
        bf16split(Wh[k * 96 + cc], g_WcT_hi[i], g_WcT_lo[i]);
    }
    if (i < 384) {
        int h = i / 96, cc = i - h * 96;
        g_bc[i] = ((h == 0) ? b0 : (h == 1) ? b1 : (h == 2) ? b2 : b3)[cc];
    }
    if (i < 65536) {                       // WfT [256 n][256 k]
        int n = i >> 8, k = i & 255;
        bf16split(Wf[(size_t)k * 256 + n], g_WfT_hi[i], g_WfT_lo[i]);
    }
    if (i < 786432) {                      // WsT [256 n][3072 k]
        int n = i / 3072, k = i - n * 3072;
        bf16split(Ws[(size_t)k * 256 + n], g_WsT_hi[i], g_WsT_lo[i]);
    }
}

// ---------------------------------------------------------------------------
// k_cvtx: x fp32 -> bf16 hi/lo (one float4 per thread).
// ---------------------------------------------------------------------------
__global__ void __launch_bounds__(256) k_cvtx(const float* __restrict__ x)
{
    const size_t i = (size_t)blockIdx.x * 256 + threadIdx.x;   // float4 index
    float4 v = ((const float4*)x)[i];
    __nv_bfloat16 h0, l0, h1, l1, h2, l2, h3, l3;
    bf16split(v.x, h0, l0); bf16split(v.y, h1, l1);
    bf16split(v.z, h2, l2); bf16split(v.w, h3, l3);
    __nv_bfloat162 hp0 = __halves2bfloat162(h0, h1), hp1 = __halves2bfloat162(h2, h3);
    __nv_bfloat162 lp0 = __halves2bfloat162(l0, l1), lp1 = __halves2bfloat162(l2, l3);
    ((uint2*)g_xh)[i] = make_uint2(*(uint32_t*)&hp0, *(uint32_t*)&hp1);
    ((uint2*)g_xl)[i] = make_uint2(*(uint32_t*)&lp0, *(uint32_t*)&lp1);
}

// ---------------------------------------------------------------------------
// k_qkv: g_qkv = x @ Wcat + bcat.  M=393216, K=128, N=384.
// ---------------------------------------------------------------------------
__global__ void __launch_bounds__(256, 2) k_qkv()
{
    const int row0 = blockIdx.x * 128, n0 = blockIdx.y * 128;
    gemm_cp(g_xh, g_xl, row0, g_WcT_hi, g_WcT_lo, n0, 128, 8,
        [&](int row, int col, float v0, float v1) {
            float2 t;
            t.x = v0 + g_bc[n0 + col];
            t.y = v1 + g_bc[n0 + col + 1];
            *(float2*)(g_qkv + (size_t)(row0 + row) * 384 + n0 + col) = t;
        });
}

// ---------------------------------------------------------------------------
// k_attn2: attention + m stats + LN1-normalized A1 (bf16 hi/lo, g1/be1 folded).
// ---------------------------------------------------------------------------
__global__ void __launch_bounds__(256) k_attn2(
    const float* __restrict__ x,
    const float* __restrict__ g1, const float* __restrict__ be1)
{
    const int tid = threadIdx.x, w = tid >> 5, lane = tid & 31;
    const int b = blockIdx.x * 8 + w;

    float qv[6][12];
#pragma unroll
    for (int s = 0; s < 6; ++s)
#pragma unroll
        for (int jj = 0; jj < 12; ++jj)
            qv[s][jj] = g_qkv[((size_t)b * 6 + s) * 384 + jj * 32 + lane];

    float xr[6][4], ssum[6], ssq[6];
#pragma unroll
    for (int s = 0; s < 6; ++s) {
        float a = 0.f, q = 0.f;
#pragma unroll
        for (int i = 0; i < 4; ++i) {
            float v = x[(size_t)b * 768 + s * 128 + lane + 32 * i];
            xr[s][i] = v;
            a += v; q += v * v;
        }
        ssum[s] = a; ssq[s] = q;
    }

    float ao[6][4];
#pragma unroll
    for (int h = 0; h < 4; ++h) {
#pragma unroll
        for (int qi = 0; qi < 6; ++qi) {
            float o = 0.f;
#pragma unroll
            for (int ki = 0; ki < 6; ++ki) {
                float p = qv[qi][3 * h] * qv[ki][3 * h + 1];
#pragma unroll
                for (int off = 16; off > 0; off >>= 1)
                    p += __shfl_xor_sync(0xffffffffu, p, off);
                o = fmaf(p, qv[ki][3 * h + 2], o);
            }
            ao[qi][h] = o;
            g_attn[((size_t)b * 6 + qi) * 128 + h * 32 + lane] = o;
            ssum[qi] += o;
            ssq[qi] += o * o;
        }
    }

#pragma unroll
    for (int s = 0; s < 6; ++s) {
        float a = ssum[s], q = ssq[s];
#pragma unroll
        for (int off = 16; off > 0; off >>= 1) {
            a += __shfl_xor_sync(0xffffffffu, a, off);
            q += __shfl_xor_sync(0xffffffffu, q, off);
        }
        const int r = b * 6 + s;
        if (lane == 0) { g_msum[r] = a; g_msumsq[r] = q; }
        const float mu = a * (1.f / 256.f);
        const float var = q * (1.f / 256.f) - mu * mu;
        const float rs = rsqrtf(var + EPS_LN);
        const size_t base = (size_t)r * 256;
#pragma unroll
        for (int i = 0; i < 4; ++i) {
            const int k = lane + 32 * i;
            const float t = fmaf((xr[s][i] - mu) * rs, g1[k], be1[k]);
            bf16split(t, g_A1h[base + k], g_A1l[base + k]);
        }
#pragma unroll
        for (int h = 0; h < 4; ++h) {
            const int k = 128 + h * 32 + lane;
            const float t = fmaf((ao[s][h] - mu) * rs, g1[k], be1[k]);
            bf16split(t, g_A1h[base + k], g_A1l[base + k]);
        }
    }
}

// ---------------------------------------------------------------------------
// k_ln1: g_n = A1 @ Wf + bf.  M=393216, K=256, N=256.
// ---------------------------------------------------------------------------
__global__ void __launch_bounds__(256, 2) k_ln1(const float* __restrict__ bf)
{
    const int row0 = blockIdx.x * 128, n0 = blockIdx.y * 128;
    gemm_cp(g_A1h, g_A1l, row0, g_WfT_hi, g_WfT_lo, n0, 256, 16,
        [&](int row, int col, float v0, float v1) {
            float2 t;
            t.x = v0 + bf[n0 + col];
            t.y = v1 + bf[n0 + col + 1];
            *(float2*)(g_n + (size_t)(row0 + row) * 256 + n0 + col) = t;
        });
}

// ---------------------------------------------------------------------------
// k_cvt2: LN2 stats over concat(n,m) + write A2 (bf16 hi/lo, g2/be2 folded).
// One warp per row r = b*6+s.  A2 k-order per row: [n 256][x 128][attn 128].
// ---------------------------------------------------------------------------
__global__ void __launch_bounds__(256) k_cvt2(
    const float* __restrict__ x,
    const float* __restrict__ g2, const float* __restrict__ be2)
{
    const int w = threadIdx.x >> 5, lane = threadIdx.x & 31;
    const int r = blockIdx.x * 8 + w;
    const int b = r / 6, s = r - b * 6;

    const float4* pn = (const float4*)(g_n + (size_t)r * 256);
    float4 n0v = pn[lane], n1v = pn[32 + lane];
    float sum = n0v.x + n0v.y + n0v.z + n0v.w + n1v.x + n1v.y + n1v.z + n1v.w;
    float sq  = n0v.x * n0v.x + n0v.y * n0v.y + n0v.z * n0v.z + n0v.w * n0v.w
              + n1v.x * n1v.x + n1v.y * n1v.y + n1v.z * n1v.z + n1v.w * n1v.w;
#pragma unroll
    for (int off = 16; off > 0; off >>= 1) {
        sum += __shfl_xor_sync(0xffffffffu, sum, off);
        sq  += __shfl_xor_sync(0xffffffffu, sq, off);
    }
    const float tot = g_msum[r] + sum, totq = g_msumsq[r] + sq;
    const float mu = tot * (1.f / 512.f);
    const float rs = rsqrtf(totq * (1.f / 512.f) - mu * mu + EPS_LN);

    const size_t base = (size_t)b * 3072 + s * 512;
    float4 xv = ((const float4*)(x + (size_t)r * 128))[lane];
    float4 av = ((const float4*)(g_attn + (size_t)r * 128))[lane];

    float4 vals[4] = {n0v, n1v, xv, av};
    const int kk[4] = {4 * lane, 128 + 4 * lane, 256 + 4 * lane, 384 + 4 * lane};
#pragma unroll
    for (int q = 0; q < 4; ++q) {
        const int k = kk[q];
        float t0 = fmaf((vals[q].x - mu) * rs, g2[k],     be2[k]);
        float t1 = fmaf((vals[q].y - mu) * rs, g2[k + 1], be2[k + 1]);
        float t2 = fmaf((vals[q].z - mu) * rs, g2[k + 2], be2[k + 2]);
        float t3 = fmaf((vals[q].w - mu) * rs, g2[k + 3], be2[k + 3]);
        __nv_bfloat16 h0, l0, h1, l1, h2, l2, h3, l3;
        bf16split(t0, h0, l0); bf16split(t1, h1, l1);
        bf16split(t2, h2, l2); bf16split(t3, h3, l3);
        __nv_bfloat162 hp0 = __halves2bfloat162(h0, h1), hp1 = __halves2bfloat162(h2, h3);
        __nv_bfloat162 lp0 = __halves2bfloat162(l0, l1), lp1 = __halves2bfloat162(l2, l3);
        *(uint2*)(g_A2h + base + k) = make_uint2(*(uint32_t*)&hp0, *(uint32_t*)&hp1);
        *(uint2*)(g_A2l + base + k) = make_uint2(*(uint32_t*)&lp0, *(uint32_t*)&lp1);
    }
}

// ---------------------------------------------------------------------------
// k_out: out = relu( A2 @ Ws + bs ).  M=65536, K=3072, N=256.
// ---------------------------------------------------------------------------
__global__ void __launch_bounds__(256, 2) k_out(
    const float* __restrict__ bs, float* __restrict__ out)
{
    const int b0 = blockIdx.x * 128, n0 = blockIdx.y * 128;
    gemm_cp(g_A2h, g_A2l, b0, g_WsT_hi, g_WsT_lo, n0, 3072, 192,
        [&](int row, int col, float v0, float v1) {
            float2 t;
            t.x = fmaxf(v0 + bs[n0 + col], 0.f);
            t.y = fmaxf(v1 + bs[n0 + col + 1], 0.f);
            *(float2*)(out + (size_t)(b0 + row) * 256 + n0 + col) = t;
        });
}

// ---------------------------------------------------------------------------
// kernel_launch: pure kernel launches (graph-capture-safe, no host API calls)
// ---------------------------------------------------------------------------
extern "C" void kernel_launch(void* const* d_in, const int* in_sizes, int n_in,
                              void* d_out, int out_size)
{
    (void)in_sizes; (void)n_in; (void)out_size;
    const float* x   = (const float*)d_in[0];
    const float* W0  = (const float*)d_in[1];
    const float* b0  = (const float*)d_in[2];
    const float* W1  = (const float*)d_in[3];
    const float* b1  = (const float*)d_in[4];
    const float* W2  = (const float*)d_in[5];
    const float* b2  = (const float*)d_in[6];
    const float* W3  = (const float*)d_in[7];
    const float* b3  = (const float*)d_in[8];
    const float* g1  = (const float*)d_in[9];
    const float* be1 = (const float*)d_in[10];
    const float* Wf  = (const float*)d_in[11];
    const float* bf  = (const float*)d_in[12];
    const float* g2  = (const float*)d_in[13];
    const float* be2 = (const float*)d_in[14];
    const float* Ws  = (const float*)d_in[15];
    const float* bs  = (const float*)d_in[16];
    float* out = (float*)d_out;

    k_prep<<<3072, 256>>>(W0, W1, W2, W3, b0, b1, b2, b3, Wf, Ws);
    k_cvtx<<<49152, 256>>>(x);
    k_qkv<<<dim3(3072, 3), 256>>>();
    k_attn2<<<8192, 256>>>(x, g1, be1);
    k_ln1<<<dim3(3072, 2), 256>>>(bf);
    k_cvt2<<<49152, 256>>>(x, g2, be2);
    k_out<<<dim3(512, 2), 256>>>(bs, out);
}